// round 12
// baseline (speedup 1.0000x reference)
#include <cuda_runtime.h>

// Correlation cost volume (FlowNet-style), MAX_DISP=4 (81 displacements).
// first, second: [B=4, C=128, H=128, W=192] fp32.  out: [B, 81, H, W] fp32,
// out[b,(dy+4)*9+(dx+4),y,x] = (1/C) * sum_c first[b,c,y,x]*second[b,c,y+dy,x+dx]
//
// v8: R7 structure (best: 72.2us) with broadcast-f adjacent-dx f32x2 pairing:
// per (ch,j) 16 ffma2 + 4 FFMA (20 math issues for 36 MACs, was 26), and all
// s-pairs read as ulonglong2 straight from smem (aligned halves of LDS.128 —
// zero pack MOVs; the R11 misaligned-pair regression is avoided).

namespace {
constexpr int Bb = 4, Cc = 128, Hh = 128, Ww = 192;
constexpr int PXT = 4;             // pixels per thread along x
constexpr int GX  = 16;            // thread columns
constexpr int TX  = GX * PXT;      // 64
constexpr int TY  = 8;
constexpr int NT  = GX * TY;       // 128 threads/block
constexpr int CCH = 8;             // channels per stage
constexpr int NST = Cc / CCH;      // 16
constexpr int SROWS = TY + 2;      // 10 second rows per dy-group of 3
constexpr int SW  = TX + 8;        // 72 floats per second row
constexpr int SROW_V4 = SW / 4;    // 18
constexpr int XT  = Ww / TX;       // 3
constexpr int YT  = Hh / TY;       // 16
constexpr int SEC_F = CCH * SROWS * SW;   // 5760 floats
constexpr int FST_F = CCH * TY * TX;      // 4096 floats
constexpr int BUF_F = SEC_F + FST_F;      // 9856 floats per pipeline buffer
constexpr unsigned SMEM_BYTES = 2u * BUF_F * 4u;  // 78848 B -> 2 blocks/SM
constexpr int NBLOCKS = Bb * XT * YT * 3;  // 576
constexpr int SEC_V4 = SEC_F / 4;          // 1440 float4 per stage
constexpr int SEC_SLOTS = 12;              // 11 full + 32-thread tail
constexpr unsigned CH_STRIDE = (unsigned)CCH * Hh * Ww * 4u;   // bytes per stage
constexpr unsigned PLANE = (unsigned)Hh * Ww * 4u;             // one channel plane
}  // namespace

__device__ __forceinline__ void cp16(unsigned sdst, const char* gsrc, unsigned sz) {
    asm volatile("cp.async.cg.shared.global [%0], [%1], 16, %2;\n"
                 :: "r"(sdst), "l"(gsrc), "r"(sz) : "memory");
}
__device__ __forceinline__ unsigned long long dup2(float x) {
    unsigned long long r;
    asm("mov.b64 %0, {%1, %1};" : "=l"(r) : "f"(x));
    return r;
}
__device__ __forceinline__ void ffma2(unsigned long long& d,
                                      unsigned long long a, unsigned long long b) {
    asm("fma.rn.f32x2 %0, %1, %2, %0;" : "+l"(d) : "l"(a), "l"(b));
}
__device__ __forceinline__ void unpack2(unsigned long long v, float& lo, float& hi) {
    asm("mov.b64 {%0, %1}, %2;" : "=f"(lo), "=f"(hi) : "l"(v));
}
__device__ __forceinline__ float lo32(unsigned long long v) {
    float a, b; unpack2(v, a, b); return a;
}
__device__ __forceinline__ float hi32(unsigned long long v) {
    float a, b; unpack2(v, a, b); return b;
}

__global__ __launch_bounds__(NT, 2)
void FunctionCorrelation_17282948399394_kernel(
    const float* __restrict__ first,
    const float* __restrict__ second,
    float* __restrict__ out)
{
    extern __shared__ float smem[];
    const unsigned smem_u32 = (unsigned)__cvta_generic_to_shared(smem);

    const int tx  = threadIdx.x;          // 0..15
    const int ty  = threadIdx.y;          // 0..7
    const int tid = ty * GX + tx;         // 0..127

    int t = blockIdx.x;
    const int g  = t % 3;  t /= 3;        // dy group: dy in {3g-4,3g-3,3g-2}
    const int xt = t % XT; t /= XT;
    const int yt = t % YT; t /= YT;
    const int b  = t;

    const int x0  = xt * TX;
    const int y0  = yt * TY;
    const int ys0 = y0 + 3 * g - 4;

    // ---- precompute second-tile load slots (stage-0 byte offsets) -----------
    unsigned secOff[SEC_SLOTS];
    unsigned vmask = 0;                   // bit s set -> in-bounds (sz=16)
#pragma unroll
    for (int s = 0; s < SEC_SLOTS; s++) {
        const int i = s * NT + tid;
        unsigned off = 0;
        if (i < SEC_V4) {
            const int ch  = i / (SROWS * SROW_V4);
            const int rem = i - ch * (SROWS * SROW_V4);
            const int r   = rem / SROW_V4;
            const int k   = rem - r * SROW_V4;
            const int gy  = ys0 + r;
            const int gx  = x0 - 4 + 4 * k;
            if ((unsigned)gy < (unsigned)Hh && (unsigned)gx < (unsigned)Ww) {
                off = (unsigned)((((b * Cc + ch) * Hh + gy) * Ww + gx) * 4);
                vmask |= 1u << s;
            }
        }
        secOff[s] = off;
    }
    // first tile: 128 threads == one channel plane per slot (ch = slot)
    const int frr = tid >> 4;             // row 0..7
    const int fkk = tid & 15;             // float4 col 0..15
    const unsigned fstOff0 =
        (unsigned)(((b * Cc * Hh + (y0 + frr)) * Ww + x0 + 4 * fkk) * 4);

    const char* secP = (const char*)second;
    const char* fstP = (const char*)first;

    auto issue_stage = [&](int buf, const char* sp, const char* fp) {
        const unsigned sbase = smem_u32 + (unsigned)buf * (BUF_F * 4u);
#pragma unroll
        for (int s = 0; s < SEC_SLOTS; s++) {
            if (s < SEC_SLOTS - 1 || tid < (SEC_V4 - (SEC_SLOTS - 1) * NT))
                cp16(sbase + (unsigned)(s * NT + tid) * 16u, sp + secOff[s],
                     ((vmask >> s) & 1u) ? 16u : 0u);
        }
        const unsigned fbase = sbase + (unsigned)SEC_F * 4u;
#pragma unroll
        for (int s = 0; s < CCH; s++) {
            cp16(fbase + (unsigned)(s * NT + tid) * 16u,
                 fp + fstOff0 + (unsigned)s * PLANE, 16u);
        }
        asm volatile("cp.async.commit_group;" ::: "memory");
    };

    // ---- accumulators --------------------------------------------------------
    // accP[j][p][k]: f32x2 pair for pixel p covering
    //   p even: (dx=2k, 2k+1),  p odd: (dx=2k+1, 2k+2),  k=0..3
    // accS[j][p]: leftover scalar (p even: dx=8, p odd: dx=0)
    unsigned long long accP[3][4][4];
    float accS[3][4];
#pragma unroll
    for (int j = 0; j < 3; j++)
#pragma unroll
        for (int p = 0; p < 4; p++) {
            accS[j][p] = 0.f;
#pragma unroll
            for (int k = 0; k < 4; k++) accP[j][p][k] = 0ull;
        }

    // ---- pipelined main loop ------------------------------------------------
    issue_stage(0, secP, fstP);
    secP += CH_STRIDE; fstP += CH_STRIDE;

#pragma unroll 1
    for (int st = 0; st < NST; st++) {
        if (st + 1 < NST) {
            issue_stage((st + 1) & 1, secP, fstP);
            secP += CH_STRIDE; fstP += CH_STRIDE;
            asm volatile("cp.async.wait_group 1;" ::: "memory");
        } else {
            asm volatile("cp.async.wait_group 0;" ::: "memory");
        }
        __syncthreads();

        const ulonglong2* secb =
            (const ulonglong2*)(smem + (st & 1) * BUF_F);
        const float4* fstb = (const float4*)(smem + (st & 1) * BUF_F + SEC_F);

#pragma unroll
        for (int ch = 0; ch < CCH; ch++) {
            const float4 f = fstb[(ch * TY + ty) * (TX / 4) + tx];
            const unsigned long long F0 = dup2(f.x);
            const unsigned long long F1 = dup2(f.y);
            const unsigned long long F2 = dup2(f.z);
            const unsigned long long F3 = dup2(f.w);
#pragma unroll
            for (int j = 0; j < 3; j++) {
                const ulonglong2* sr =
                    secb + (ch * SROWS + ty + j) * SROW_V4 + tx;
                const ulonglong2 a2 = sr[0], c2 = sr[1], e2 = sr[2];
                // P[i] = (s[2i], s[2i+1]); s[0..11] over the 12-float window
                const unsigned long long P0 = a2.x, P1 = a2.y;
                const unsigned long long P2 = c2.x, P3 = c2.y;
                const unsigned long long P4 = e2.x, P5 = e2.y;
                // pixel 0 (even): pairs use P0..P3; scalar dx=8 -> s8 = lo(P4)
                ffma2(accP[j][0][0], F0, P0);
                ffma2(accP[j][0][1], F0, P1);
                ffma2(accP[j][0][2], F0, P2);
                ffma2(accP[j][0][3], F0, P3);
                accS[j][0] += f.x * lo32(P4);
                // pixel 1 (odd): pairs use P1..P4; scalar dx=0 -> s1 = hi(P0)
                ffma2(accP[j][1][0], F1, P1);
                ffma2(accP[j][1][1], F1, P2);
                ffma2(accP[j][1][2], F1, P3);
                ffma2(accP[j][1][3], F1, P4);
                accS[j][1] += f.y * hi32(P0);
                // pixel 2 (even): pairs use P1..P4; scalar dx=8 -> s10 = lo(P5)
                ffma2(accP[j][2][0], F2, P1);
                ffma2(accP[j][2][1], F2, P2);
                ffma2(accP[j][2][2], F2, P3);
                ffma2(accP[j][2][3], F2, P4);
                accS[j][2] += f.z * lo32(P5);
                // pixel 3 (odd): pairs use P2..P5; scalar dx=0 -> s3 = hi(P1)
                ffma2(accP[j][3][0], F3, P2);
                ffma2(accP[j][3][1], F3, P3);
                ffma2(accP[j][3][2], F3, P4);
                ffma2(accP[j][3][3], F3, P5);
                accS[j][3] += f.w * hi32(P1);
            }
        }
        __syncthreads();   // all reads of this buffer done before it is refilled
    }

    // ---- epilogue: unpack to r[pixel][dx], write 27 planes as float4 --------
    const float inv = 1.0f / (float)Cc;
    const int x = x0 + tx * PXT;
    const int y = y0 + ty;
#pragma unroll
    for (int j = 0; j < 3; j++) {
        float r[4][9];
#pragma unroll
        for (int p = 0; p < 4; p++) {
            if ((p & 1) == 0) {           // even pixel: pairs at dx (2k,2k+1)
#pragma unroll
                for (int k = 0; k < 4; k++)
                    unpack2(accP[j][p][k], r[p][2 * k], r[p][2 * k + 1]);
                r[p][8] = accS[j][p];
            } else {                      // odd pixel: pairs at dx (2k+1,2k+2)
                r[p][0] = accS[j][p];
#pragma unroll
                for (int k = 0; k < 4; k++)
                    unpack2(accP[j][p][k], r[p][2 * k + 1], r[p][2 * k + 2]);
            }
        }
        const int dyi = 3 * g + j;
#pragma unroll
        for (int d = 0; d < 9; d++) {
            *reinterpret_cast<float4*>(out + ((b * 81 + dyi * 9 + d) * Hh + y) * Ww + x) =
                make_float4(r[0][d] * inv, r[1][d] * inv,
                            r[2][d] * inv, r[3][d] * inv);
        }
    }
}

extern "C" void kernel_launch(void* const* d_in, const int* in_sizes, int n_in,
                              void* d_out, int out_size)
{
    const float* first  = (const float*)d_in[0];
    const float* second = (const float*)d_in[1];
    float* out          = (float*)d_out;

    cudaFuncSetAttribute(FunctionCorrelation_17282948399394_kernel,
                         cudaFuncAttributeMaxDynamicSharedMemorySize,
                         (int)SMEM_BYTES);

    dim3 block(GX, TY, 1);
    FunctionCorrelation_17282948399394_kernel<<<NBLOCKS, block, SMEM_BYTES>>>(
        first, second, out);
}